// round 15
// baseline (speedup 1.0000x reference)
#include <cuda_runtime.h>
#include <cuda_fp16.h>

typedef unsigned int u32;

#define NCONV 8
#define HO 62
#define WO 62
#define PX 48        // bytes per feature pixel (32 data + 16 pad -> conflict-free ldmatrix)
#define TROWS 6      // input rows per band tile
#define BAND_R 4     // output rows per block

__device__ __forceinline__ u32 smem_u32(const void* p) {
    u32 a;
    asm("{ .reg .u64 t; cvta.to.shared.u64 t, %1; cvt.u32.u64 %0, t; }" : "=r"(a) : "l"(p));
    return a;
}
// pack two f32 -> f16x2 (first arg in low half)
__device__ __forceinline__ u32 pack_h2(float lo, float hi) {
    u32 r; asm("cvt.rn.f16x2.f32 %0, %1, %2;" : "=r"(r) : "f"(hi), "f"(lo)); return r;
}
__device__ __forceinline__ void ldsm_x4(u32 &r0, u32 &r1, u32 &r2, u32 &r3, u32 addr) {
    asm volatile("ldmatrix.sync.aligned.m8n8.x4.shared.b16 {%0,%1,%2,%3}, [%4];"
                 : "=r"(r0), "=r"(r1), "=r"(r2), "=r"(r3) : "r"(addr));
}
__device__ __forceinline__ void mma_k16(float c[4], u32 a0, u32 a1, u32 a2, u32 a3,
                                        u32 b0, u32 b1) {
    asm volatile(
        "mma.sync.aligned.m16n8k16.row.col.f32.f16.f16.f32 "
        "{%0,%1,%2,%3}, {%4,%5,%6,%7}, {%8,%9}, {%0,%1,%2,%3};"
        : "+f"(c[0]), "+f"(c[1]), "+f"(c[2]), "+f"(c[3])
        : "r"(a0), "r"(a1), "r"(a2), "r"(a3), "r"(b0), "r"(b1));
}

__global__ __launch_bounds__(128, 8)
void kan_hmma5(const float* __restrict__ x,
               const float* __restrict__ base_w,
               const float* __restrict__ spline_w,
               const float* __restrict__ spline_s,
               const float* __restrict__ grid_,
               float* __restrict__ out) {
    // feature tile: TROWS x 64 pixels, 16 fp16 (k16 vector) + 16B pad each
    __shared__ __align__(16) char   s_feat[TROWS * 64 * PX];   // 18432 B
    __shared__ __align__(16) __half s_bt[9 * 8 * 16];          // 2304 B [tap][n][k]

    const int tid  = threadIdx.x;
    const int w    = tid >> 5;
    const int lane = tid & 31;
    const int band = blockIdx.x;      // 0..15 (4 output rows each; band 15 has 2)
    const int img  = blockIdx.y;      // 0..255
    const int y0   = band * BAND_R;

    // ---- B staging: k0/k9=bw_hi, k1..8=spline, k10=bw_lo (fp16 compensated base) ----
    for (int idx = tid; idx < 9 * 8 * 16; idx += 128) {
        int tap = idx >> 7, rem = idx & 127, n = rem >> 4, k = rem & 15;
        __half hv = __float2half_rn(0.0f);
        if (k == 0 || k == 9) {
            hv = __float2half_rn(base_w[n * 9 + tap]);
        } else if (k <= 8) {
            hv = __float2half_rn(spline_w[(n * 9 + tap) * NCONV + (k - 1)]
                                 * spline_s[n * 9 + tap]);
        } else if (k == 10) {
            float bw = base_w[n * 9 + tap];
            hv = __float2half_rn(bw - __half2float(__float2half_rn(bw)));
        }
        s_bt[idx] = hv;
    }

    const float g0    = grid_[0];
    const float inv_h = 1.0f / (grid_[1] - grid_[0]);

    // ---- A-build: per pixel, k16 vec = [silu, b0..b7, slo, silu, 0x5] ----
    const float* xin = x + img * 4096;
    #pragma unroll
    for (int e = tid; e < TROWS * 64; e += 128) {   // 384 = 3 * 128
        int row = e >> 6, col = e & 63;
        int yin = y0 + row; if (yin > 63) yin = 63;  // band-15 clamp (outputs masked)
        float v = xin[yin * 64 + col];

        float sig  = 1.0f / (1.0f + __expf(-v));
        float silu = v * sig;
        float slo  = silu - __half2float(__float2half_rn(silu));

        float u  = (v - g0) * inv_h;
        float fj = floorf(u);
        int   j0 = (int)fj;
        float tt = u - fj;
        float t2 = tt * tt, t3 = t2 * tt, om = 1.0f - tt;
        const float s6 = 1.0f / 6.0f;
        float c0 = om * om * om * s6;
        float c1 = (3.0f * t3 - 6.0f * t2 + 4.0f) * s6;
        float c2 = (-3.0f * t3 + 3.0f * t2 + 3.0f * tt + 1.0f) * s6;
        float c3 = t3 * s6;
        int jb = j0 - 3;     // basis index of c0

        char* bp = s_feat + e * PX;
        // h0=silu, h1..7=0 ; h8=0, h9=slo, h10=silu, h11..15=0
        *(uint4*)bp        = make_uint4(pack_h2(silu, 0.0f), 0u, 0u, 0u);
        *(uint4*)(bp + 16) = make_uint4(pack_h2(0.0f, slo), pack_h2(silu, 0.0f), 0u, 0u);
        // basis slots h(1+jb+k) for k=0..3, guarded to 0<=jb+k<=7
        int jj;
        jj = jb;     if (jj >= 0 && jj <= 7) *(__half*)(bp + (1 + jj) * 2) = __float2half_rn(c0);
        jj = jb + 1; if (jj >= 0 && jj <= 7) *(__half*)(bp + (1 + jj) * 2) = __float2half_rn(c1);
        jj = jb + 2; if (jj >= 0 && jj <= 7) *(__half*)(bp + (1 + jj) * 2) = __float2half_rn(c2);
        jj = jb + 3; if (jj >= 0 && jj <= 7) *(__half*)(bp + (1 + jj) * 2) = __float2half_rn(c3);
    }
    __syncthreads();

    // ---- B fragments (k16 col layout) ----
    u32 bf0[9], bf1[9];
    {
        const __half* bb = s_bt + (lane >> 2) * 16 + 2 * (lane & 3);
        #pragma unroll
        for (int tap = 0; tap < 9; ++tap) {
            bf0[tap] = *(const u32*)(bb + tap * 128);
            bf1[tap] = *(const u32*)(bb + tap * 128 + 8);
        }
    }

    // ---- tensor phase: warp w -> output row y0+w; 4 m16 tiles ----
    // tile x-bases {0,16,32,46}: last overlaps so all pixels valid, no x-guards
    const u32 fb = smem_u32(s_feat);
    u32 ab[4];
    #pragma unroll
    for (int tau = 0; tau < 4; ++tau) {
        int xb = (tau == 3) ? 46 : tau * 16;
        ab[tau] = fb + (u32)((w * 64 + xb + (lane & 15)) * PX) + (u32)((lane >> 4) * 16);
    }

    float c[4][4];
    #pragma unroll
    for (int tau = 0; tau < 4; ++tau)
        #pragma unroll
        for (int i = 0; i < 4; ++i) c[tau][i] = 0.0f;

    #pragma unroll
    for (int tap = 0; tap < 9; ++tap) {
        const int dy = tap / 3, dx = tap % 3;
        const u32 off = (u32)((dy * 64 + dx) * PX);
        #pragma unroll
        for (int tau = 0; tau < 4; ++tau) {
            u32 a0, a1, a2, a3;
            ldsm_x4(a0, a1, a2, a3, ab[tau] + off);
            mma_k16(c[tau], a0, a1, a2, a3, bf0[tap], bf1[tap]);
        }
    }

    // ---- store: c rows = pixel x, c cols = conv n ----
    const int n0 = 2 * (lane & 3);
    const int y  = y0 + w;
    if (y < HO) {
        #pragma unroll
        for (int tau = 0; tau < 4; ++tau) {
            int xb = (tau == 3) ? 46 : tau * 16;
            #pragma unroll
            for (int g = 0; g < 2; ++g) {
                int xo = xb + g * 8 + (lane >> 2);        // <= 61 always
                float* p = out + ((img * NCONV + n0) * HO + y) * WO + xo;
                p[0]       = c[tau][g * 2 + 0];
                p[HO * WO] = c[tau][g * 2 + 1];
            }
        }
    }
}

extern "C" void kernel_launch(void* const* d_in, const int* in_sizes, int n_in,
                              void* d_out, int out_size) {
    const float* x  = (const float*)d_in[0];
    const float* bw = (const float*)d_in[1];
    const float* sw = (const float*)d_in[2];
    const float* ss = (const float*)d_in[3];
    const float* gr = (const float*)d_in[4];
    float* out = (float*)d_out;

    dim3 grd(16, 256);   // 16 four-row bands x 256 images
    kan_hmma5<<<grd, 128>>>(x, bw, sw, ss, gr, out);
}

// round 16
// speedup vs baseline: 1.2214x; 1.2214x over previous
#include <cuda_runtime.h>
#include <cuda_fp16.h>

typedef unsigned int u32;

#define NCONV 8
#define HO 62
#define WO 62
#define TROWS 10     // input rows per band tile
#define NPX   (TROWS * 64)

__device__ __forceinline__ u32 smem_u32(const void* p) {
    u32 a;
    asm("{ .reg .u64 t; cvta.to.shared.u64 t, %1; cvt.u32.u64 %0, t; }" : "=r"(a) : "l"(p));
    return a;
}
// pack two f32 -> f16x2 (first arg in low half)
__device__ __forceinline__ u32 pack_h2(float lo, float hi) {
    u32 r; asm("cvt.rn.f16x2.f32 %0, %1, %2;" : "=r"(r) : "f"(hi), "f"(lo)); return r;
}
__device__ __forceinline__ void ldsm_x4(u32 &r0, u32 &r1, u32 &r2, u32 &r3, u32 addr) {
    asm volatile("ldmatrix.sync.aligned.m8n8.x4.shared.b16 {%0,%1,%2,%3}, [%4];"
                 : "=r"(r0), "=r"(r1), "=r"(r2), "=r"(r3) : "r"(addr));
}
__device__ __forceinline__ void mma_k16(float c[4], u32 a0, u32 a1, u32 a2, u32 a3,
                                        u32 b0, u32 b1) {
    asm volatile(
        "mma.sync.aligned.m16n8k16.row.col.f32.f16.f16.f32 "
        "{%0,%1,%2,%3}, {%4,%5,%6,%7}, {%8,%9}, {%0,%1,%2,%3};"
        : "+f"(c[0]), "+f"(c[1]), "+f"(c[2]), "+f"(c[3])
        : "r"(a0), "r"(a1), "r"(a2), "r"(a3), "r"(b0), "r"(b1));
}

__global__ __launch_bounds__(128, 8)
void kan_hmma6(const float* __restrict__ x,
               const float* __restrict__ base_w,
               const float* __restrict__ spline_w,
               const float* __restrict__ spline_s,
               const float* __restrict__ grid_,
               float* __restrict__ out) {
    // split k16 feature vector: fa = halves k0..7, fb = halves k8..15 (16B each)
    __shared__ __align__(16) uint4  s_fa[NPX];            // 10240 B
    __shared__ __align__(16) uint4  s_fb[NPX];            // 10240 B
    __shared__ __align__(16) __half s_bt[9 * 8 * 16];     // 2304 B [tap][n][k]

    const int tid  = threadIdx.x;
    const int w    = tid >> 5;
    const int lane = tid & 31;
    const int band = blockIdx.x;      // 0..7  (8 output rows; band 7 has 6)
    const int img  = blockIdx.y;      // 0..255
    const int y0   = band * 8;

    // ---- B staging: k0/k9=bw_hi, k1..8=spline, k10=bw_lo (fp16 compensated) ----
    for (int idx = tid; idx < 9 * 8 * 16; idx += 128) {
        int tap = idx >> 7, rem = idx & 127, n = rem >> 4, k = rem & 15;
        __half hv = __float2half_rn(0.0f);
        if (k == 0 || k == 9) {
            hv = __float2half_rn(base_w[n * 9 + tap]);
        } else if (k <= 8) {
            hv = __float2half_rn(spline_w[(n * 9 + tap) * NCONV + (k - 1)]
                                 * spline_s[n * 9 + tap]);
        } else if (k == 10) {
            float bw = base_w[n * 9 + tap];
            hv = __float2half_rn(bw - __half2float(__float2half_rn(bw)));
        }
        s_bt[idx] = hv;
    }

    const float g0    = grid_[0];
    const float inv_h = 1.0f / (grid_[1] - grid_[0]);

    // ---- A-build: k16 vec = [silu, b0..b7, slo, silu, 0x5] split fa/fb ----
    const float* xin = x + img * 4096;
    #pragma unroll
    for (int e = tid; e < NPX; e += 128) {    // 640 = 5 * 128
        int row = e >> 6, col = e & 63;
        int yin = y0 + row; if (yin > 63) yin = 63;   // band-7 clamp (outputs masked)
        float v = xin[yin * 64 + col];

        float sig  = 1.0f / (1.0f + __expf(-v));
        float silu = v * sig;
        float slo  = silu - __half2float(__float2half_rn(silu));

        float u  = (v - g0) * inv_h;
        float fj = floorf(u);
        int   j0 = (int)fj;
        float tt = u - fj;
        float t2 = tt * tt, t3 = t2 * tt, om = 1.0f - tt;
        const float s6 = 1.0f / 6.0f;
        float c0 = om * om * om * s6;
        float c1 = (3.0f * t3 - 6.0f * t2 + 4.0f) * s6;
        float c2 = (-3.0f * t3 + 3.0f * t2 + 3.0f * tt + 1.0f) * s6;
        float c3 = t3 * s6;
        int jb = j0 - 3;     // basis index of c0

        // fa: h0=silu, h1..7 = b0..b6 (default 0)
        s_fa[e] = make_uint4(pack_h2(silu, 0.0f), 0u, 0u, 0u);
        // fb: h8=b7(default 0), h9=slo, h10=silu, h11..15=0
        s_fb[e] = make_uint4(pack_h2(0.0f, slo), pack_h2(silu, 0.0f), 0u, 0u);

        // guarded basis stores: slot h(1+jj) -> fa halves 1..7, fb half 0 (jj==7)
        __half* fah = (__half*)&s_fa[e];
        __half* fbh = (__half*)&s_fb[e];
        int jj;
        jj = jb;     if (jj >= 0) { if (jj < 7) fah[1 + jj] = __float2half_rn(c0); else if (jj == 7) fbh[0] = __float2half_rn(c0); }
        jj = jb + 1; if (jj >= 0) { if (jj < 7) fah[1 + jj] = __float2half_rn(c1); else if (jj == 7) fbh[0] = __float2half_rn(c1); }
        jj = jb + 2; if (jj >= 0) { if (jj < 7) fah[1 + jj] = __float2half_rn(c2); else if (jj == 7) fbh[0] = __float2half_rn(c2); }
        jj = jb + 3; if (jj >= 0) { if (jj < 7) fah[1 + jj] = __float2half_rn(c3); else if (jj == 7) fbh[0] = __float2half_rn(c3); }
    }
    __syncthreads();

    // ---- tensor phase: warp w -> output rows y0+2w, y0+2w+1; 4 tiles/row ----
    // tile x-bases {0,16,32,46}: last overlaps -> all pixels valid, no x-guards
    const u32 fa0 = smem_u32(s_fa);
    const u32 fb0 = smem_u32(s_fb);
    const u32 fsel = (lane < 16) ? fa0 : fb0;     // lanes 0-15: k0..7, 16-31: k8..15
    const __half* bb = s_bt + (lane >> 2) * 16 + 2 * (lane & 3);

    u32 ab[8];
    #pragma unroll
    for (int tau = 0; tau < 8; ++tau) {
        int r  = w * 2 + (tau >> 2);
        int xb = ((tau & 3) == 3) ? 46 : (tau & 3) * 16;
        ab[tau] = fsel + (u32)((r * 64 + xb + (lane & 15)) * 16);
    }

    float c[8][4];
    #pragma unroll
    for (int tau = 0; tau < 8; ++tau)
        #pragma unroll
        for (int i = 0; i < 4; ++i) c[tau][i] = 0.0f;

    #pragma unroll
    for (int tap = 0; tap < 9; ++tap) {
        const int dy = tap / 3, dx = tap % 3;
        const u32 off = (u32)((dy * 64 + dx) * 16);
        const u32 b0 = *(const u32*)(bb + tap * 128);
        const u32 b1 = *(const u32*)(bb + tap * 128 + 8);
        #pragma unroll
        for (int tau = 0; tau < 8; ++tau) {
            u32 a0, a1, a2, a3;
            ldsm_x4(a0, a1, a2, a3, ab[tau] + off);
            mma_k16(c[tau], a0, a1, a2, a3, b0, b1);
        }
    }

    // ---- store: c rows = pixel x, c cols = conv n ----
    const int n0 = 2 * (lane & 3);
    #pragma unroll
    for (int tau = 0; tau < 8; ++tau) {
        int y = y0 + w * 2 + (tau >> 2);
        if (y < HO) {
            int xb = ((tau & 3) == 3) ? 46 : (tau & 3) * 16;
            #pragma unroll
            for (int g = 0; g < 2; ++g) {
                int xo = xb + g * 8 + (lane >> 2);        // <= 61 always
                float* p = out + ((img * NCONV + n0) * HO + y) * WO + xo;
                p[0]       = c[tau][g * 2 + 0];
                p[HO * WO] = c[tau][g * 2 + 1];
            }
        }
    }
}

extern "C" void kernel_launch(void* const* d_in, const int* in_sizes, int n_in,
                              void* d_out, int out_size) {
    const float* x  = (const float*)d_in[0];
    const float* bw = (const float*)d_in[1];
    const float* sw = (const float*)d_in[2];
    const float* ss = (const float*)d_in[3];
    const float* gr = (const float*)d_in[4];
    float* out = (float*)d_out;

    dim3 grd(8, 256);   // 8 eight-row bands x 256 images
    kan_hmma6<<<grd, 128>>>(x, bw, sw, ss, gr, out);
}